// round 7
// baseline (speedup 1.0000x reference)
#include <cuda_runtime.h>
#include <cuda_bf16.h>
#include <cstdint>

// ---------------- problem constants ----------------
#define NN     50000
#define IN_C   128
#define HID    64
#define HEADS  4
#define OUT_C  64
#define EMAX   800000
#define ETOT   (EMAX + NN)     // with self loops

typedef unsigned long long ull;

// ---------------- scratch (device globals; no allocation allowed) ----------
__device__ float g_h [ (size_t)NN * (HEADS*HID) ]; // GEMM output / features h
__device__ float g_x [ (size_t)NN * (HEADS*HID) ]; // layer output / next GEMM input
__device__ float g_as[ NN * HEADS ];
__device__ float g_ad[ NN * HEADS ];
__device__ int   g_off[ NN + 1 ];
__device__ int   g_cnt[ NN ];
__device__ int   g_cur[ NN ];
__device__ int   g_srt[ ETOT ];
__device__ float g_sum[ HID ];
__device__ int   g_is64;          // edge_index dtype flag (auto-detected)
__device__ int   g_bsum[ 256 ];   // scan: per-block sums
__device__ int   g_bpre[ 256 ];   // scan: per-block exclusive prefixes

// ---------------- packed f32x2 helpers ----------------
__device__ __forceinline__ void fma2(ull& d, ull a, ull b) {
    asm("fma.rn.f32x2 %0, %1, %2, %3;" : "=l"(d) : "l"(a), "l"(b), "l"(d));
}
__device__ __forceinline__ float2 unpk(ull u) {
    float2 r;
    asm("mov.b64 {%0, %1}, %2;" : "=f"(r.x), "=f"(r.y) : "l"(u));
    return r;
}

// ---------------- edge_index dtype detection ----------------
__global__ void detect_kernel(const int* __restrict__ ei32) {
    if (threadIdx.x == 0 && blockIdx.x == 0) {
        int odd_or = 0;
#pragma unroll
        for (int i = 0; i < 64; i++) odd_or |= ei32[2 * i + 1];
        g_is64 = (odd_or == 0) ? 1 : 0;
    }
}

__device__ __forceinline__ int edge_src(const int* ei32, int E, int i) {
    return g_is64 ? ei32[2 * i] : ei32[i];
}
__device__ __forceinline__ int edge_dst(const int* ei32, int E, int i) {
    return g_is64 ? ei32[2 * (E + i)] : ei32[E + i];
}

// ---------------- CSR build ----------------
__global__ void init_cnt_kernel(int n) {
    int i = blockIdx.x * blockDim.x + threadIdx.x;
    if (i < n) g_cnt[i] = 1;   // self loop
}

__global__ void hist_kernel(const int* __restrict__ ei, int E) {
    int i = blockIdx.x * blockDim.x + threadIdx.x;
    if (i < E) atomicAdd(&g_cnt[edge_dst(ei, E, i)], 1);
}

// --- 3-phase parallel scan over g_cnt -> g_off / g_cur ---
__global__ void scan1_kernel(int n) {        // per-block sums
    __shared__ int sh[256];
    int t = threadIdx.x;
    int i = blockIdx.x * 256 + t;
    sh[t] = (i < n) ? g_cnt[i] : 0;
    __syncthreads();
#pragma unroll
    for (int d = 128; d; d >>= 1) {
        if (t < d) sh[t] += sh[t + d];
        __syncthreads();
    }
    if (t == 0) g_bsum[blockIdx.x] = sh[0];
}

__global__ void scan2_kernel(int nb, int n) { // scan the (<=256) block sums
    __shared__ int sh[256];
    int t = threadIdx.x;
    int v = (t < nb) ? g_bsum[t] : 0;
    sh[t] = v;
    __syncthreads();
#pragma unroll
    for (int d = 1; d < 256; d <<= 1) {
        int u = (t >= d) ? sh[t - d] : 0;
        __syncthreads();
        sh[t] += u;
        __syncthreads();
    }
    g_bpre[t] = sh[t] - v;                    // exclusive
    if (t == 255) g_off[n] = sh[255];
}

__global__ void scan3_kernel(int n) {         // per-block rescan + base
    __shared__ int sh[256];
    int t = threadIdx.x;
    int i = blockIdx.x * 256 + t;
    int c = (i < n) ? g_cnt[i] : 0;
    sh[t] = c;
    __syncthreads();
#pragma unroll
    for (int d = 1; d < 256; d <<= 1) {
        int u = (t >= d) ? sh[t - d] : 0;
        __syncthreads();
        sh[t] += u;
        __syncthreads();
    }
    if (i < n) {
        int ex = sh[t] - c + g_bpre[blockIdx.x];
        g_off[i] = ex;
        g_cur[i] = ex;
    }
}

__global__ void scatter_kernel(const int* __restrict__ ei, int E, int n) {
    int i = blockIdx.x * blockDim.x + threadIdx.x;
    int total = E + n;
    if (i >= total) return;
    int s, d;
    if (i < E) { s = edge_src(ei, E, i); d = edge_dst(ei, E, i); }
    else       { s = d = i - E; }
    int pos = atomicAdd(&g_cur[d], 1);
    g_srt[pos] = s;
}

// ---------------- SGEMM (packed f32x2): g_h[N,M] = A[N,K] @ B[K,M] ----------
// BM=128 BN=64 BK=16, 256 threads. Per thread: 8 rows (4 packed pairs) x 4 cols.
// B tile stored DUPLICATED in smem so an LDS.128 yields broadcast f32x2 pairs.
template<bool FROM_GLOBAL>
__global__ __launch_bounds__(256) void sgemm_kernel(
    const float* __restrict__ Ain, const float* __restrict__ B,
    int Nrows, int K, int M)
{
    const float* A = FROM_GLOBAL ? g_x : Ain;
    float* C = g_h;
    __shared__ float As[16][128];
    __shared__ float Bd[16][128];  // duplicated: Bd[k][2c+{0,1}] = B[k][col0+c]
    int tid  = threadIdx.x;
    int row0 = blockIdx.y * 128;
    int col0 = blockIdx.x * 64;
    int tx = tid & 15;       // col group: 4 cols each
    int ty = tid >> 4;       // row group: 8 rows each

    ull acc[4][4];
#pragma unroll
    for (int i = 0; i < 4; i++)
#pragma unroll
        for (int j = 0; j < 4; j++) acc[i][j] = 0ull;  // {+0.f,+0.f}

    for (int k0 = 0; k0 < K; k0 += 16) {
        // load A tile 128x16 (512 float4), transposed into As[k][row]
#pragma unroll
        for (int s = 0; s < 2; s++) {
            int idx = tid + s * 256;
            int r   = idx >> 2;
            int c4  = idx & 3;
            int grow = row0 + r;
            float4 v = make_float4(0.f, 0.f, 0.f, 0.f);
            if (grow < Nrows)
                v = *reinterpret_cast<const float4*>(A + (size_t)grow * K + k0 + c4 * 4);
            As[c4 * 4 + 0][r] = v.x;
            As[c4 * 4 + 1][r] = v.y;
            As[c4 * 4 + 2][r] = v.z;
            As[c4 * 4 + 3][r] = v.w;
        }
        // load B tile 16x64 duplicated (each thread: 4 cols -> 2 float4 stores)
        {
            int r  = tid >> 4;    // k 0..15
            int c4 = tid & 15;    // 0..15
            float4 v = *reinterpret_cast<const float4*>(B + (size_t)(k0 + r) * M + col0 + c4 * 4);
            float4 d0 = make_float4(v.x, v.x, v.y, v.y);
            float4 d1 = make_float4(v.z, v.z, v.w, v.w);
            *reinterpret_cast<float4*>(&Bd[r][c4 * 8])     = d0;
            *reinterpret_cast<float4*>(&Bd[r][c4 * 8 + 4]) = d1;
        }
        __syncthreads();
#pragma unroll
        for (int k = 0; k < 16; k++) {
            ulonglong2 a0 = *reinterpret_cast<const ulonglong2*>(&As[k][ty * 8]);
            ulonglong2 a1 = *reinterpret_cast<const ulonglong2*>(&As[k][ty * 8 + 4]);
            ulonglong2 b0 = *reinterpret_cast<const ulonglong2*>(&Bd[k][tx * 8]);
            ulonglong2 b1 = *reinterpret_cast<const ulonglong2*>(&Bd[k][tx * 8 + 4]);
            ull ap[4] = { a0.x, a0.y, a1.x, a1.y };   // row pairs
            ull bp[4] = { b0.x, b0.y, b1.x, b1.y };   // col broadcasts
#pragma unroll
            for (int i = 0; i < 4; i++)
#pragma unroll
                for (int j = 0; j < 4; j++)
                    fma2(acc[i][j], ap[i], bp[j]);
        }
        __syncthreads();
    }
#pragma unroll
    for (int i = 0; i < 4; i++) {
        float2 c0 = unpk(acc[i][0]);
        float2 c1 = unpk(acc[i][1]);
        float2 c2 = unpk(acc[i][2]);
        float2 c3 = unpk(acc[i][3]);
        int r0 = row0 + ty * 8 + 2 * i;
        if (r0 < Nrows) {
            float4 v = make_float4(c0.x, c1.x, c2.x, c3.x);
            *reinterpret_cast<float4*>(C + (size_t)r0 * M + col0 + tx * 4) = v;
        }
        if (r0 + 1 < Nrows) {
            float4 v = make_float4(c0.y, c1.y, c2.y, c3.y);
            *reinterpret_cast<float4*>(C + (size_t)(r0 + 1) * M + col0 + tx * 4) = v;
        }
    }
}

// ---------------- attention coefficients: alpha_s/alpha_d per node ----------
template<int H>
__global__ void alpha_kernel(const float* __restrict__ a_s,
                             const float* __restrict__ a_d, int n)
{
    int w = (blockIdx.x * blockDim.x + threadIdx.x) >> 5;
    int lane = threadIdx.x & 31;
    if (w >= n) return;
    constexpr int FPL = 2 * H;
    float ps[H], pd[H];
#pragma unroll
    for (int hh = 0; hh < H; hh++) { ps[hh] = 0.f; pd[hh] = 0.f; }
    const float* row = g_h + (size_t)w * (H * 64);
#pragma unroll
    for (int j = 0; j < FPL; j++) {
        float v = row[lane + 32 * j];
        int hh = j >> 1;
        int c  = lane + 32 * (j & 1);
        ps[hh] += v * a_s[hh * 64 + c];
        pd[hh] += v * a_d[hh * 64 + c];
    }
#pragma unroll
    for (int hh = 0; hh < H; hh++) {
        float s = ps[hh], d = pd[hh];
#pragma unroll
        for (int o = 16; o; o >>= 1) {
            s += __shfl_xor_sync(0xffffffffu, s, o);
            d += __shfl_xor_sync(0xffffffffu, d, o);
        }
        if (lane == 0) { g_as[w * H + hh] = s; g_ad[w * H + hh] = d; }
    }
}

// ---------------- fused edge softmax + aggregation (one warp per dst) -------
// Lane owns columns 64*h + 2*lane, 2*lane+1 for each head h -> float2 traffic.
template<int H, bool RELU>
__global__ __launch_bounds__(256) void agg_kernel(
    const float* __restrict__ bias, int n)
{
    int w = (blockIdx.x * blockDim.x + threadIdx.x) >> 5;
    int lane = threadIdx.x & 31;
    if (w >= n) return;
    constexpr int FEAT = H * 64;

    float adv[H];
#pragma unroll
    for (int hh = 0; hh < H; hh++) adv[hh] = g_ad[w * H + hh];

    float m[H], den[H];
    float2 acc[H];
#pragma unroll
    for (int hh = 0; hh < H; hh++) {
        m[hh] = -1e30f; den[hh] = 0.f;
        acc[hh] = make_float2(0.f, 0.f);
    }

    int e1 = g_off[w + 1];
    for (int e = g_off[w]; e < e1; e++) {
        int s = g_srt[e];                       // same for all lanes -> broadcast
        const float* hr = g_h + (size_t)s * FEAT + 2 * lane;
        float2 v[H];
#pragma unroll
        for (int hh = 0; hh < H; hh++)
            v[hh] = *reinterpret_cast<const float2*>(hr + 64 * hh);

        float asv[H];
        if constexpr (H == 4) {
            float4 t = *reinterpret_cast<const float4*>(g_as + (size_t)s * 4);
            asv[0] = t.x; asv[1] = t.y; asv[2] = t.z; asv[3] = t.w;
        } else {
            asv[0] = g_as[s];
        }
#pragma unroll
        for (int hh = 0; hh < H; hh++) {
            float eh = asv[hh] + adv[hh];
            eh = (eh > 0.f) ? eh : 0.2f * eh;     // leaky_relu(0.2)
            float wgt;
            if (eh > m[hh]) {
                float sc = __expf(m[hh] - eh);    // exp(-inf)=0 on first edge
                den[hh] = den[hh] * sc + 1.f;
                acc[hh].x *= sc;
                acc[hh].y *= sc;
                m[hh] = eh;
                wgt = 1.f;
            } else {
                wgt = __expf(eh - m[hh]);
                den[hh] += wgt;
            }
            acc[hh].x += wgt * v[hh].x;
            acc[hh].y += wgt * v[hh].y;
        }
    }
#pragma unroll
    for (int hh = 0; hh < H; hh++) {
        int col = 64 * hh + 2 * lane;
        float rden = 1.f / den[hh];
        float o0 = acc[hh].x * rden + bias[col];
        float o1 = acc[hh].y * rden + bias[col + 1];
        if (RELU) { o0 = fmaxf(o0, 0.f); o1 = fmaxf(o1, 0.f); }
        *reinterpret_cast<float2*>(g_x + (size_t)w * FEAT + col) = make_float2(o0, o1);
    }
}

// ---------------- mean over nodes + linear head ----------------
__global__ void zero_sum_kernel() {
    g_sum[threadIdx.x] = 0.f;
}

__global__ void colsum_kernel(int n) {
    int col = threadIdx.x;                 // 64 threads
    int r0 = blockIdx.x * 256;
    int r1 = r0 + 256; if (r1 > n) r1 = n;
    float s = 0.f;
    for (int r = r0; r < r1; r++) s += g_x[(size_t)r * 64 + col];
    atomicAdd(&g_sum[col], s);
}

__global__ void head_kernel(const float* __restrict__ hw,
                            const float* __restrict__ hb,
                            float* __restrict__ out, int n) {
    __shared__ float g[64];
    int t = threadIdx.x;
    g[t] = g_sum[t] / (float)n;
    __syncthreads();
    float o = hb[t];
#pragma unroll
    for (int c = 0; c < 64; c++) o += g[c] * hw[c * 64 + t];
    out[t] = o;
}

// ---------------- launch (kernel launches ONLY; graph-capturable) ----------
extern "C" void kernel_launch(void* const* d_in, const int* in_sizes, int n_in,
                              void* d_out, int out_size) {
    const float* x   = (const float*)d_in[0];
    const int*   ei  = (const int*)d_in[1];     // int32 OR int64 (auto-detected)
    const float* W0  = (const float*)d_in[2];
    const float* a0s = (const float*)d_in[3];
    const float* a0d = (const float*)d_in[4];
    const float* b0  = (const float*)d_in[5];
    const float* W1  = (const float*)d_in[6];
    const float* a1s = (const float*)d_in[7];
    const float* a1d = (const float*)d_in[8];
    const float* b1  = (const float*)d_in[9];
    const float* W2  = (const float*)d_in[10];
    const float* a2s = (const float*)d_in[11];
    const float* a2d = (const float*)d_in[12];
    const float* b2  = (const float*)d_in[13];
    const float* hw  = (const float*)d_in[14];
    const float* hb  = (const float*)d_in[15];
    float* out = (float*)d_out;

    const int N = in_sizes[0] / IN_C;
    const int E = in_sizes[1] / 2;   // element count is dtype-independent

    // ---- CSR by dst (recomputed each launch; deterministic work) ----
    const int NB = (N + 255) / 256;
    detect_kernel<<<1, 32>>>(ei);
    init_cnt_kernel<<<NB, 256>>>(N);
    hist_kernel<<<(E + 255) / 256, 256>>>(ei, E);
    scan1_kernel<<<NB, 256>>>(N);
    scan2_kernel<<<1, 256>>>(NB, N);
    scan3_kernel<<<NB, 256>>>(N);
    scatter_kernel<<<((E + N) + 255) / 256, 256>>>(ei, E, N);

    const int warpBlocks = (N * 32 + 255) / 256;

    // ---- layer 0: 128 -> 4x64 ----
    {
        dim3 g(256 / 64, (N + 127) / 128);
        sgemm_kernel<false><<<g, 256>>>(x, W0, N, 128, 256);
    }
    alpha_kernel<4><<<warpBlocks, 256>>>(a0s, a0d, N);
    agg_kernel<4, true><<<warpBlocks, 256>>>(b0, N);

    // ---- layer 1: 256 -> 4x64 ----
    {
        dim3 g(256 / 64, (N + 127) / 128);
        sgemm_kernel<true><<<g, 256>>>(nullptr, W1, N, 256, 256);
    }
    alpha_kernel<4><<<warpBlocks, 256>>>(a1s, a1d, N);
    agg_kernel<4, true><<<warpBlocks, 256>>>(b1, N);

    // ---- layer 2: 256 -> 1x64 (no relu) ----
    {
        dim3 g(64 / 64, (N + 127) / 128);
        sgemm_kernel<true><<<g, 256>>>(nullptr, W2, N, 256, 64);
    }
    alpha_kernel<1><<<warpBlocks, 256>>>(a2s, a2d, N);
    agg_kernel<1, false><<<warpBlocks, 256>>>(b2, N);

    // ---- mean over nodes + linear head ----
    zero_sum_kernel<<<1, 64>>>();
    colsum_kernel<<<NB, 64>>>(N);
    head_kernel<<<1, 64>>>(hw, hb, out, N);
}

// round 9
// speedup vs baseline: 1.3029x; 1.3029x over previous
#include <cuda_runtime.h>
#include <cuda_bf16.h>
#include <cstdint>

// ---------------- problem constants ----------------
#define NN     50000
#define IN_C   128
#define HID    64
#define HEADS  4
#define OUT_C  64
#define EMAX   800000
#define ETOT   (EMAX + NN)     // with self loops

// ---------------- scratch (device globals; no allocation allowed) ----------
__device__ float g_h [ (size_t)NN * (HEADS*HID) ]; // GEMM output / features h
__device__ float g_x [ (size_t)NN * (HEADS*HID) ]; // layer output / next GEMM input
__device__ float g_as[ NN * HEADS ];
__device__ float g_ad[ NN * HEADS ];
__device__ int   g_off[ NN + 1 ];
__device__ int   g_cnt[ NN ];
__device__ int   g_cur[ NN ];
__device__ int   g_srt[ ETOT ];
__device__ float g_sum[ HID ];
__device__ int   g_is64;          // edge_index dtype flag (auto-detected)
__device__ int   g_bsum[ 256 ];   // scan: per-block sums
__device__ int   g_bpre[ 256 ];   // scan: per-block exclusive prefixes

// ---------------- edge_index dtype detection ----------------
__global__ void detect_kernel(const int* __restrict__ ei32) {
    if (threadIdx.x == 0 && blockIdx.x == 0) {
        int odd_or = 0;
#pragma unroll
        for (int i = 0; i < 64; i++) odd_or |= ei32[2 * i + 1];
        g_is64 = (odd_or == 0) ? 1 : 0;
    }
}

__device__ __forceinline__ int edge_src(const int* ei32, int E, int i) {
    return g_is64 ? ei32[2 * i] : ei32[i];
}
__device__ __forceinline__ int edge_dst(const int* ei32, int E, int i) {
    return g_is64 ? ei32[2 * (E + i)] : ei32[E + i];
}

// ---------------- CSR build ----------------
__global__ void init_cnt_kernel(int n) {
    int i = blockIdx.x * blockDim.x + threadIdx.x;
    if (i < n) g_cnt[i] = 1;   // self loop
}

__global__ void hist_kernel(const int* __restrict__ ei, int E) {
    int i = blockIdx.x * blockDim.x + threadIdx.x;
    if (i < E) atomicAdd(&g_cnt[edge_dst(ei, E, i)], 1);
}

// --- 3-phase parallel scan over g_cnt -> g_off / g_cur ---
__global__ void scan1_kernel(int n) {        // per-block sums
    __shared__ int sh[256];
    int t = threadIdx.x;
    int i = blockIdx.x * 256 + t;
    sh[t] = (i < n) ? g_cnt[i] : 0;
    __syncthreads();
#pragma unroll
    for (int d = 128; d; d >>= 1) {
        if (t < d) sh[t] += sh[t + d];
        __syncthreads();
    }
    if (t == 0) g_bsum[blockIdx.x] = sh[0];
}

__global__ void scan2_kernel(int nb, int n) { // scan the (<=256) block sums
    __shared__ int sh[256];
    int t = threadIdx.x;
    int v = (t < nb) ? g_bsum[t] : 0;
    sh[t] = v;
    __syncthreads();
#pragma unroll
    for (int d = 1; d < 256; d <<= 1) {
        int u = (t >= d) ? sh[t - d] : 0;
        __syncthreads();
        sh[t] += u;
        __syncthreads();
    }
    g_bpre[t] = sh[t] - v;                    // exclusive
    if (t == 255) g_off[n] = sh[255];
}

__global__ void scan3_kernel(int n) {         // per-block rescan + base
    __shared__ int sh[256];
    int t = threadIdx.x;
    int i = blockIdx.x * 256 + t;
    int c = (i < n) ? g_cnt[i] : 0;
    sh[t] = c;
    __syncthreads();
#pragma unroll
    for (int d = 1; d < 256; d <<= 1) {
        int u = (t >= d) ? sh[t - d] : 0;
        __syncthreads();
        sh[t] += u;
        __syncthreads();
    }
    if (i < n) {
        int ex = sh[t] - c + g_bpre[blockIdx.x];
        g_off[i] = ex;
        g_cur[i] = ex;
    }
}

__global__ void scatter_kernel(const int* __restrict__ ei, int E, int n) {
    int i = blockIdx.x * blockDim.x + threadIdx.x;
    int total = E + n;
    if (i >= total) return;
    int s, d;
    if (i < E) { s = edge_src(ei, E, i); d = edge_dst(ei, E, i); }
    else       { s = d = i - E; }
    int pos = atomicAdd(&g_cur[d], 1);
    g_srt[pos] = s;
}

// ---------------- SGEMM: g_h[N,M] = A[N,K] @ B[K,M] ----------------
// A = external input (FROM_GLOBAL=false) or g_x (FROM_GLOBAL=true).
// BM=128 BN=64 BK=16, 256 threads, 8x4 microtile. K % 16 == 0, M % 64 == 0.
template<bool FROM_GLOBAL>
__global__ __launch_bounds__(256) void sgemm_kernel(
    const float* __restrict__ Ain, const float* __restrict__ B,
    int Nrows, int K, int M)
{
    const float* A = FROM_GLOBAL ? g_x : Ain;
    float* C = g_h;
    __shared__ float As[16][128];
    __shared__ float Bs[16][64];
    int tid  = threadIdx.x;
    int row0 = blockIdx.y * 128;
    int col0 = blockIdx.x * 64;
    int tx = tid & 15;       // col group 0..15 (4 cols each)
    int ty = tid >> 4;       // row group 0..15 (8 rows each)

    float acc[8][4];
#pragma unroll
    for (int i = 0; i < 8; i++)
#pragma unroll
        for (int j = 0; j < 4; j++) acc[i][j] = 0.f;

    for (int k0 = 0; k0 < K; k0 += 16) {
        // load A tile 128x16 (512 float4)
#pragma unroll
        for (int s = 0; s < 2; s++) {
            int idx = tid + s * 256;
            int r   = idx >> 2;
            int c4  = idx & 3;
            int grow = row0 + r;
            float4 v = make_float4(0.f, 0.f, 0.f, 0.f);
            if (grow < Nrows)
                v = *reinterpret_cast<const float4*>(A + (size_t)grow * K + k0 + c4 * 4);
            As[c4 * 4 + 0][r] = v.x;
            As[c4 * 4 + 1][r] = v.y;
            As[c4 * 4 + 2][r] = v.z;
            As[c4 * 4 + 3][r] = v.w;
        }
        // load B tile 16x64 (256 float4)
        {
            int r  = tid >> 4;    // k 0..15
            int c4 = tid & 15;    // 0..15
            float4 v = *reinterpret_cast<const float4*>(B + (size_t)(k0 + r) * M + col0 + c4 * 4);
            *reinterpret_cast<float4*>(&Bs[r][c4 * 4]) = v;
        }
        __syncthreads();
#pragma unroll
        for (int k = 0; k < 16; k++) {
            float a[8], b[4];
            float4 a0 = *reinterpret_cast<const float4*>(&As[k][ty * 8]);
            float4 a1 = *reinterpret_cast<const float4*>(&As[k][ty * 8 + 4]);
            a[0]=a0.x; a[1]=a0.y; a[2]=a0.z; a[3]=a0.w;
            a[4]=a1.x; a[5]=a1.y; a[6]=a1.z; a[7]=a1.w;
            float4 b0 = *reinterpret_cast<const float4*>(&Bs[k][tx * 4]);
            b[0]=b0.x; b[1]=b0.y; b[2]=b0.z; b[3]=b0.w;
#pragma unroll
            for (int i = 0; i < 8; i++)
#pragma unroll
                for (int j = 0; j < 4; j++)
                    acc[i][j] += a[i] * b[j];
        }
        __syncthreads();
    }
#pragma unroll
    for (int i = 0; i < 8; i++) {
        int grow = row0 + ty * 8 + i;
        if (grow < Nrows) {
            float4 v = make_float4(acc[i][0], acc[i][1], acc[i][2], acc[i][3]);
            *reinterpret_cast<float4*>(C + (size_t)grow * M + col0 + tx * 4) = v;
        }
    }
}

// ---------------- attention coefficients: alpha_s/alpha_d per node ----------
// reads g_h, writes g_as/g_ad
template<int H>
__global__ void alpha_kernel(const float* __restrict__ a_s,
                             const float* __restrict__ a_d, int n)
{
    int w = (blockIdx.x * blockDim.x + threadIdx.x) >> 5;
    int lane = threadIdx.x & 31;
    if (w >= n) return;
    constexpr int FPL = 2 * H;
    float ps[H], pd[H];
#pragma unroll
    for (int hh = 0; hh < H; hh++) { ps[hh] = 0.f; pd[hh] = 0.f; }
    const float* row = g_h + (size_t)w * (H * 64);
#pragma unroll
    for (int j = 0; j < FPL; j++) {
        float v = row[lane + 32 * j];
        int hh = j >> 1;
        int c  = lane + 32 * (j & 1);
        ps[hh] += v * a_s[hh * 64 + c];
        pd[hh] += v * a_d[hh * 64 + c];
    }
#pragma unroll
    for (int hh = 0; hh < H; hh++) {
        float s = ps[hh], d = pd[hh];
#pragma unroll
        for (int o = 16; o; o >>= 1) {
            s += __shfl_xor_sync(0xffffffffu, s, o);
            d += __shfl_xor_sync(0xffffffffu, d, o);
        }
        if (lane == 0) { g_as[w * H + hh] = s; g_ad[w * H + hh] = d; }
    }
}

// ---------------- fused edge softmax + aggregation (one warp per dst) -------
// reads g_h/g_as/g_ad/g_off/g_srt, writes g_x
template<int FPL, int H, bool RELU>
__global__ __launch_bounds__(256) void agg_kernel(
    const float* __restrict__ bias, int n)
{
    int w = (blockIdx.x * blockDim.x + threadIdx.x) >> 5;
    int lane = threadIdx.x & 31;
    if (w >= n) return;
    constexpr int FEAT = FPL * 32;

    float adv[H];
#pragma unroll
    for (int hh = 0; hh < H; hh++) adv[hh] = g_ad[w * H + hh];

    float m[H], den[H], acc[FPL];
#pragma unroll
    for (int hh = 0; hh < H; hh++) { m[hh] = -1e30f; den[hh] = 0.f; }
#pragma unroll
    for (int j = 0; j < FPL; j++) acc[j] = 0.f;

    int e1 = g_off[w + 1];
    for (int e = g_off[w]; e < e1; e++) {
        int s = g_srt[e];                       // same for all lanes -> broadcast
        const float* hr = g_h + (size_t)s * FEAT;
        float v[FPL];
#pragma unroll
        for (int j = 0; j < FPL; j++) v[j] = hr[lane + 32 * j];

        float asv[H];
        if constexpr (H == 4) {
            float4 t = *reinterpret_cast<const float4*>(g_as + (size_t)s * 4);
            asv[0] = t.x; asv[1] = t.y; asv[2] = t.z; asv[3] = t.w;
        } else {
            asv[0] = g_as[s];
        }
#pragma unroll
        for (int hh = 0; hh < H; hh++) {
            float eh = asv[hh] + adv[hh];
            eh = (eh > 0.f) ? eh : 0.2f * eh;     // leaky_relu(0.2)
            float wgt;
            if (eh > m[hh]) {
                float sc = __expf(m[hh] - eh);    // exp(-inf)=0 on first edge
                den[hh] = den[hh] * sc + 1.f;
                acc[2 * hh]     *= sc;
                acc[2 * hh + 1] *= sc;
                m[hh] = eh;
                wgt = 1.f;
            } else {
                wgt = __expf(eh - m[hh]);
                den[hh] += wgt;
            }
            acc[2 * hh]     += wgt * v[2 * hh];
            acc[2 * hh + 1] += wgt * v[2 * hh + 1];
        }
    }
#pragma unroll
    for (int j = 0; j < FPL; j++) {
        int col = lane + 32 * j;
        float o = acc[j] / den[j >> 1] + bias[col];
        if (RELU) o = fmaxf(o, 0.f);
        g_x[(size_t)w * FEAT + col] = o;
    }
}

// ---------------- mean over nodes + linear head ----------------
__global__ void zero_sum_kernel() {
    g_sum[threadIdx.x] = 0.f;
}

__global__ void colsum_kernel(int n) {
    int col = threadIdx.x;                 // 64 threads
    int r0 = blockIdx.x * 256;
    int r1 = r0 + 256; if (r1 > n) r1 = n;
    float s = 0.f;
    for (int r = r0; r < r1; r++) s += g_x[(size_t)r * 64 + col];
    atomicAdd(&g_sum[col], s);
}

__global__ void head_kernel(const float* __restrict__ hw,
                            const float* __restrict__ hb,
                            float* __restrict__ out, int n) {
    __shared__ float g[64];
    int t = threadIdx.x;
    g[t] = g_sum[t] / (float)n;
    __syncthreads();
    float o = hb[t];
#pragma unroll
    for (int c = 0; c < 64; c++) o += g[c] * hw[c * 64 + t];
    out[t] = o;
}

// ---------------- launch (kernel launches ONLY; graph-capturable) ----------
extern "C" void kernel_launch(void* const* d_in, const int* in_sizes, int n_in,
                              void* d_out, int out_size) {
    const float* x   = (const float*)d_in[0];
    const int*   ei  = (const int*)d_in[1];     // int32 OR int64 (auto-detected)
    const float* W0  = (const float*)d_in[2];
    const float* a0s = (const float*)d_in[3];
    const float* a0d = (const float*)d_in[4];
    const float* b0  = (const float*)d_in[5];
    const float* W1  = (const float*)d_in[6];
    const float* a1s = (const float*)d_in[7];
    const float* a1d = (const float*)d_in[8];
    const float* b1  = (const float*)d_in[9];
    const float* W2  = (const float*)d_in[10];
    const float* a2s = (const float*)d_in[11];
    const float* a2d = (const float*)d_in[12];
    const float* b2  = (const float*)d_in[13];
    const float* hw  = (const float*)d_in[14];
    const float* hb  = (const float*)d_in[15];
    float* out = (float*)d_out;

    const int N = in_sizes[0] / IN_C;
    const int E = in_sizes[1] / 2;   // element count is dtype-independent

    // ---- CSR by dst (recomputed each launch; deterministic work) ----
    const int NB = (N + 255) / 256;
    detect_kernel<<<1, 32>>>(ei);
    init_cnt_kernel<<<NB, 256>>>(N);
    hist_kernel<<<(E + 255) / 256, 256>>>(ei, E);
    scan1_kernel<<<NB, 256>>>(N);
    scan2_kernel<<<1, 256>>>(NB, N);
    scan3_kernel<<<NB, 256>>>(N);
    scatter_kernel<<<((E + N) + 255) / 256, 256>>>(ei, E, N);

    const int warpBlocks = (N * 32 + 255) / 256;

    // ---- layer 0: 128 -> 4x64 ----
    {
        dim3 g(256 / 64, (N + 127) / 128);
        sgemm_kernel<false><<<g, 256>>>(x, W0, N, 128, 256);
    }
    alpha_kernel<4><<<warpBlocks, 256>>>(a0s, a0d, N);
    agg_kernel<8, 4, true><<<warpBlocks, 256>>>(b0, N);

    // ---- layer 1: 256 -> 4x64 ----
    {
        dim3 g(256 / 64, (N + 127) / 128);
        sgemm_kernel<true><<<g, 256>>>(nullptr, W1, N, 256, 256);
    }
    alpha_kernel<4><<<warpBlocks, 256>>>(a1s, a1d, N);
    agg_kernel<8, 4, true><<<warpBlocks, 256>>>(b1, N);

    // ---- layer 2: 256 -> 1x64 (no relu) ----
    {
        dim3 g(64 / 64, (N + 127) / 128);
        sgemm_kernel<true><<<g, 256>>>(nullptr, W2, N, 256, 64);
    }
    alpha_kernel<1><<<warpBlocks, 256>>>(a2s, a2d, N);
    agg_kernel<2, 1, false><<<warpBlocks, 256>>>(b2, N);

    // ---- mean over nodes + linear head ----
    zero_sum_kernel<<<1, 64>>>();
    colsum_kernel<<<NB, 64>>>(N);
    head_kernel<<<1, 64>>>(hw, hb, out, N);
}

// round 13
// speedup vs baseline: 1.3678x; 1.0498x over previous
#include <cuda_runtime.h>
#include <cuda_bf16.h>
#include <cstdint>

// ---------------- problem constants ----------------
#define NN     50000
#define IN_C   128
#define HID    64
#define HEADS  4
#define OUT_C  64
#define EMAX   800000
#define ETOT   (EMAX + NN)     // with self loops

// ---------------- scratch (device globals; no allocation allowed) ----------
__device__ float g_h [ (size_t)NN * (HEADS*HID) ]; // GEMM output / features h
__device__ float g_x [ (size_t)NN * (HEADS*HID) ]; // layer output / next GEMM input
__device__ float g_as[ NN * HEADS ];
__device__ float g_ad[ NN * HEADS ];
__device__ int   g_off[ NN + 1 ];
__device__ int   g_cnt[ NN ];
__device__ int   g_cur[ NN ];
__device__ int   g_srt[ ETOT ];
__device__ float g_sum[ HID ];
__device__ int   g_is64;          // edge_index dtype flag (auto-detected)
__device__ int   g_bsum[ 256 ];   // scan: per-block sums
__device__ int   g_bpre[ 256 ];   // scan: per-block exclusive prefixes

// ---------------- edge_index dtype detection ----------------
__global__ void detect_kernel(const int* __restrict__ ei32) {
    if (threadIdx.x == 0 && blockIdx.x == 0) {
        int odd_or = 0;
#pragma unroll
        for (int i = 0; i < 64; i++) odd_or |= ei32[2 * i + 1];
        g_is64 = (odd_or == 0) ? 1 : 0;
    }
}

__device__ __forceinline__ int edge_src(const int* ei32, int E, int i) {
    return g_is64 ? ei32[2 * i] : ei32[i];
}
__device__ __forceinline__ int edge_dst(const int* ei32, int E, int i) {
    return g_is64 ? ei32[2 * (E + i)] : ei32[E + i];
}

// ---------------- CSR build ----------------
__global__ void init_cnt_kernel(int n) {
    int i = blockIdx.x * blockDim.x + threadIdx.x;
    if (i < n) g_cnt[i] = 1;   // self loop
}

__global__ void hist_kernel(const int* __restrict__ ei, int E) {
    int i = blockIdx.x * blockDim.x + threadIdx.x;
    if (i < E) atomicAdd(&g_cnt[edge_dst(ei, E, i)], 1);
}

// --- 3-phase parallel scan over g_cnt -> g_off / g_cur ---
__global__ void scan1_kernel(int n) {        // per-block sums
    __shared__ int sh[256];
    int t = threadIdx.x;
    int i = blockIdx.x * 256 + t;
    sh[t] = (i < n) ? g_cnt[i] : 0;
    __syncthreads();
#pragma unroll
    for (int d = 128; d; d >>= 1) {
        if (t < d) sh[t] += sh[t + d];
        __syncthreads();
    }
    if (t == 0) g_bsum[blockIdx.x] = sh[0];
}

__global__ void scan2_kernel(int nb, int n) { // scan the (<=256) block sums
    __shared__ int sh[256];
    int t = threadIdx.x;
    int v = (t < nb) ? g_bsum[t] : 0;
    sh[t] = v;
    __syncthreads();
#pragma unroll
    for (int d = 1; d < 256; d <<= 1) {
        int u = (t >= d) ? sh[t - d] : 0;
        __syncthreads();
        sh[t] += u;
        __syncthreads();
    }
    g_bpre[t] = sh[t] - v;                    // exclusive
    if (t == 255) g_off[n] = sh[255];
}

__global__ void scan3_kernel(int n) {         // per-block rescan + base
    __shared__ int sh[256];
    int t = threadIdx.x;
    int i = blockIdx.x * 256 + t;
    int c = (i < n) ? g_cnt[i] : 0;
    sh[t] = c;
    __syncthreads();
#pragma unroll
    for (int d = 1; d < 256; d <<= 1) {
        int u = (t >= d) ? sh[t - d] : 0;
        __syncthreads();
        sh[t] += u;
        __syncthreads();
    }
    if (i < n) {
        int ex = sh[t] - c + g_bpre[blockIdx.x];
        g_off[i] = ex;
        g_cur[i] = ex;
    }
}

__global__ void scatter_kernel(const int* __restrict__ ei, int E, int n) {
    int i = blockIdx.x * blockDim.x + threadIdx.x;
    int total = E + n;
    if (i >= total) return;
    int s, d;
    if (i < E) { s = edge_src(ei, E, i); d = edge_dst(ei, E, i); }
    else       { s = d = i - E; }
    int pos = atomicAdd(&g_cur[d], 1);
    g_srt[pos] = s;
}

// ---------------- tf32 helpers ----------------
__device__ __forceinline__ unsigned f2tf32(float x) {
    unsigned u;
    asm("cvt.rna.tf32.f32 %0, %1;" : "=r"(u) : "f"(x));
    return u;
}
__device__ __forceinline__ void mma_tf32(float* d, const unsigned* a, const unsigned* b) {
    asm volatile(
        "mma.sync.aligned.m16n8k8.row.col.f32.tf32.tf32.f32 "
        "{%0,%1,%2,%3}, {%4,%5,%6,%7}, {%8,%9}, {%0,%1,%2,%3};\n"
        : "+f"(d[0]), "+f"(d[1]), "+f"(d[2]), "+f"(d[3])
        : "r"(a[0]), "r"(a[1]), "r"(a[2]), "r"(a[3]), "r"(b[0]), "r"(b[1]));
}

// ---------------- GEMM (3xTF32 mma.sync): g_h[N,M] = A[N,K] @ B[K,M] -------
// BM=128 BN=64 BK=32, 256 threads (8 warps), warp tile 32x32.
// x = hi + lo split per operand; D += Ah*Bh + Al*Bh + Ah*Bl  (error ~2^-22).
#define AS_STRIDE 36
#define BS_STRIDE 72
template<bool FROM_GLOBAL>
__global__ __launch_bounds__(256) void mma_gemm_kernel(
    const float* __restrict__ Ain, const float* __restrict__ B,
    int Nrows, int K, int M)
{
    const float* A = FROM_GLOBAL ? g_x : Ain;
    float* C = g_h;
    __shared__ float As[128][AS_STRIDE];   // [row][k]
    __shared__ float Bs[32][BS_STRIDE];    // [k][n]

    int tid  = threadIdx.x;
    int lane = tid & 31;
    int wid  = tid >> 5;
    int row0 = blockIdx.y * 128;
    int col0 = blockIdx.x * 64;
    int wm = (wid >> 1) * 32;     // warp row offset in block tile
    int wn = (wid & 1) * 32;      // warp col offset
    int gq = lane >> 2;           // group id   (0..7)
    int tg = lane & 3;            // thread-in-group (0..3)

    float acc[2][4][4];
#pragma unroll
    for (int mf = 0; mf < 2; mf++)
#pragma unroll
        for (int nf = 0; nf < 4; nf++)
#pragma unroll
            for (int e = 0; e < 4; e++) acc[mf][nf][e] = 0.f;

    for (int k0 = 0; k0 < K; k0 += 32) {
        // ---- load A tile 128x32 (1024 float4, 4 per thread) ----
#pragma unroll
        for (int i = 0; i < 4; i++) {
            int idx = tid + i * 256;
            int r   = idx >> 3;
            int c4  = idx & 7;
            int grow = row0 + r;
            float4 v = make_float4(0.f, 0.f, 0.f, 0.f);
            if (grow < Nrows)
                v = *reinterpret_cast<const float4*>(A + (size_t)grow * K + k0 + c4 * 4);
            *reinterpret_cast<float4*>(&As[r][c4 * 4]) = v;
        }
        // ---- load B tile 32x64 (512 float4, 2 per thread) ----
#pragma unroll
        for (int i = 0; i < 2; i++) {
            int idx = tid + i * 256;
            int r   = idx >> 4;
            int c4  = idx & 15;
            float4 v = *reinterpret_cast<const float4*>(B + (size_t)(k0 + r) * M + col0 + c4 * 4);
            *reinterpret_cast<float4*>(&Bs[r][c4 * 4]) = v;
        }
        __syncthreads();

#pragma unroll
        for (int ks = 0; ks < 4; ks++) {
            int k8 = ks * 8;
            // A fragments: a0:(g,t) a1:(g+8,t) a2:(g,t+4) a3:(g+8,t+4)
            unsigned ah[2][4], al[2][4];
#pragma unroll
            for (int mf = 0; mf < 2; mf++) {
                int rbase = wm + mf * 16 + gq;
#pragma unroll
                for (int e = 0; e < 4; e++) {
                    int r = rbase + (e & 1) * 8;
                    int c = k8 + tg + (e >> 1) * 4;
                    float x  = As[r][c];
                    unsigned h = f2tf32(x);
                    ah[mf][e] = h;
                    al[mf][e] = f2tf32(x - __uint_as_float(h));
                }
            }
            // B fragments: b0:(k=t, n=g) b1:(k=t+4, n=g)
            unsigned bh[4][2], bl[4][2];
#pragma unroll
            for (int nf = 0; nf < 4; nf++) {
                int nidx = wn + nf * 8 + gq;
#pragma unroll
                for (int e = 0; e < 2; e++) {
                    float x  = Bs[k8 + tg + e * 4][nidx];
                    unsigned h = f2tf32(x);
                    bh[nf][e] = h;
                    bl[nf][e] = f2tf32(x - __uint_as_float(h));
                }
            }
#pragma unroll
            for (int mf = 0; mf < 2; mf++)
#pragma unroll
                for (int nf = 0; nf < 4; nf++) {
                    mma_tf32(acc[mf][nf], ah[mf], bh[nf]);
                    mma_tf32(acc[mf][nf], al[mf], bh[nf]);
                    mma_tf32(acc[mf][nf], ah[mf], bl[nf]);
                }
        }
        __syncthreads();
    }

    // ---- epilogue: c0:(g, 2t) c1:(g, 2t+1) c2:(g+8, 2t) c3:(g+8, 2t+1) ----
#pragma unroll
    for (int mf = 0; mf < 2; mf++) {
#pragma unroll
        for (int nf = 0; nf < 4; nf++) {
            int r = row0 + wm + mf * 16 + gq;
            int c = col0 + wn + nf * 8 + tg * 2;
            if (r < Nrows)
                *reinterpret_cast<float2*>(C + (size_t)r * M + c) =
                    make_float2(acc[mf][nf][0], acc[mf][nf][1]);
            if (r + 8 < Nrows)
                *reinterpret_cast<float2*>(C + (size_t)(r + 8) * M + c) =
                    make_float2(acc[mf][nf][2], acc[mf][nf][3]);
        }
    }
}

// ---------------- attention coefficients: alpha_s/alpha_d per node ----------
// reads g_h, writes g_as/g_ad
template<int H>
__global__ void alpha_kernel(const float* __restrict__ a_s,
                             const float* __restrict__ a_d, int n)
{
    int w = (blockIdx.x * blockDim.x + threadIdx.x) >> 5;
    int lane = threadIdx.x & 31;
    if (w >= n) return;
    constexpr int FPL = 2 * H;
    float ps[H], pd[H];
#pragma unroll
    for (int hh = 0; hh < H; hh++) { ps[hh] = 0.f; pd[hh] = 0.f; }
    const float* row = g_h + (size_t)w * (H * 64);
#pragma unroll
    for (int j = 0; j < FPL; j++) {
        float v = row[lane + 32 * j];
        int hh = j >> 1;
        int c  = lane + 32 * (j & 1);
        ps[hh] += v * a_s[hh * 64 + c];
        pd[hh] += v * a_d[hh * 64 + c];
    }
#pragma unroll
    for (int hh = 0; hh < H; hh++) {
        float s = ps[hh], d = pd[hh];
#pragma unroll
        for (int o = 16; o; o >>= 1) {
            s += __shfl_xor_sync(0xffffffffu, s, o);
            d += __shfl_xor_sync(0xffffffffu, d, o);
        }
        if (lane == 0) { g_as[w * H + hh] = s; g_ad[w * H + hh] = d; }
    }
}

// ---------------- fused edge softmax + aggregation (one warp per dst) -------
// reads g_h/g_as/g_ad/g_off/g_srt, writes g_x
template<int FPL, int H, bool RELU>
__global__ __launch_bounds__(256) void agg_kernel(
    const float* __restrict__ bias, int n)
{
    int w = (blockIdx.x * blockDim.x + threadIdx.x) >> 5;
    int lane = threadIdx.x & 31;
    if (w >= n) return;
    constexpr int FEAT = FPL * 32;

    float adv[H];
#pragma unroll
    for (int hh = 0; hh < H; hh++) adv[hh] = g_ad[w * H + hh];

    float m[H], den[H], acc[FPL];
#pragma unroll
    for (int hh = 0; hh < H; hh++) { m[hh] = -1e30f; den[hh] = 0.f; }
#pragma unroll
    for (int j = 0; j < FPL; j++) acc[j] = 0.f;

    int e1 = g_off[w + 1];
    for (int e = g_off[w]; e < e1; e++) {
        int s = g_srt[e];                       // same for all lanes -> broadcast
        const float* hr = g_h + (size_t)s * FEAT;
        float v[FPL];
#pragma unroll
        for (int j = 0; j < FPL; j++) v[j] = hr[lane + 32 * j];

        float asv[H];
        if constexpr (H == 4) {
            float4 t = *reinterpret_cast<const float4*>(g_as + (size_t)s * 4);
            asv[0] = t.x; asv[1] = t.y; asv[2] = t.z; asv[3] = t.w;
        } else {
            asv[0] = g_as[s];
        }
#pragma unroll
        for (int hh = 0; hh < H; hh++) {
            float eh = asv[hh] + adv[hh];
            eh = (eh > 0.f) ? eh : 0.2f * eh;     // leaky_relu(0.2)
            float wgt;
            if (eh > m[hh]) {
                float sc = __expf(m[hh] - eh);    // exp(-inf)=0 on first edge
                den[hh] = den[hh] * sc + 1.f;
                acc[2 * hh]     *= sc;
                acc[2 * hh + 1] *= sc;
                m[hh] = eh;
                wgt = 1.f;
            } else {
                wgt = __expf(eh - m[hh]);
                den[hh] += wgt;
            }
            acc[2 * hh]     += wgt * v[2 * hh];
            acc[2 * hh + 1] += wgt * v[2 * hh + 1];
        }
    }
#pragma unroll
    for (int j = 0; j < FPL; j++) {
        int col = lane + 32 * j;
        float o = acc[j] / den[j >> 1] + bias[col];
        if (RELU) o = fmaxf(o, 0.f);
        g_x[(size_t)w * FEAT + col] = o;
    }
}

// ---------------- mean over nodes + linear head ----------------
__global__ void zero_sum_kernel() {
    g_sum[threadIdx.x] = 0.f;
}

__global__ void colsum_kernel(int n) {
    int col = threadIdx.x;                 // 64 threads
    int r0 = blockIdx.x * 256;
    int r1 = r0 + 256; if (r1 > n) r1 = n;
    float s = 0.f;
    for (int r = r0; r < r1; r++) s += g_x[(size_t)r * 64 + col];
    atomicAdd(&g_sum[col], s);
}

__global__ void head_kernel(const float* __restrict__ hw,
                            const float* __restrict__ hb,
                            float* __restrict__ out, int n) {
    __shared__ float g[64];
    int t = threadIdx.x;
    g[t] = g_sum[t] / (float)n;
    __syncthreads();
    float o = hb[t];
#pragma unroll
    for (int c = 0; c < 64; c++) o += g[c] * hw[c * 64 + t];
    out[t] = o;
}

// ---------------- launch (kernel launches ONLY; graph-capturable) ----------
extern "C" void kernel_launch(void* const* d_in, const int* in_sizes, int n_in,
                              void* d_out, int out_size) {
    const float* x   = (const float*)d_in[0];
    const int*   ei  = (const int*)d_in[1];     // int32 OR int64 (auto-detected)
    const float* W0  = (const float*)d_in[2];
    const float* a0s = (const float*)d_in[3];
    const float* a0d = (const float*)d_in[4];
    const float* b0  = (const float*)d_in[5];
    const float* W1  = (const float*)d_in[6];
    const float* a1s = (const float*)d_in[7];
    const float* a1d = (const float*)d_in[8];
    const float* b1  = (const float*)d_in[9];
    const float* W2  = (const float*)d_in[10];
    const float* a2s = (const float*)d_in[11];
    const float* a2d = (const float*)d_in[12];
    const float* b2  = (const float*)d_in[13];
    const float* hw  = (const float*)d_in[14];
    const float* hb  = (const float*)d_in[15];
    float* out = (float*)d_out;

    const int N = in_sizes[0] / IN_C;
    const int E = in_sizes[1] / 2;   // element count is dtype-independent

    // ---- CSR by dst (recomputed each launch; deterministic work) ----
    const int NB = (N + 255) / 256;
    detect_kernel<<<1, 32>>>(ei);
    init_cnt_kernel<<<NB, 256>>>(N);
    hist_kernel<<<(E + 255) / 256, 256>>>(ei, E);
    scan1_kernel<<<NB, 256>>>(N);
    scan2_kernel<<<1, 256>>>(NB, N);
    scan3_kernel<<<NB, 256>>>(N);
    scatter_kernel<<<((E + N) + 255) / 256, 256>>>(ei, E, N);

    const int warpBlocks = (N * 32 + 255) / 256;
    const int gy = (N + 127) / 128;

    // ---- layer 0: 128 -> 4x64 ----
    mma_gemm_kernel<false><<<dim3(4, gy), 256>>>(x, W0, N, 128, 256);
    alpha_kernel<4><<<warpBlocks, 256>>>(a0s, a0d, N);
    agg_kernel<8, 4, true><<<warpBlocks, 256>>>(b0, N);

    // ---- layer 1: 256 -> 4x64 ----
    mma_gemm_kernel<true><<<dim3(4, gy), 256>>>(nullptr, W1, N, 256, 256);
    alpha_kernel<4><<<warpBlocks, 256>>>(a1s, a1d, N);
    agg_kernel<8, 4, true><<<warpBlocks, 256>>>(b1, N);

    // ---- layer 2: 256 -> 1x64 (no relu) ----
    mma_gemm_kernel<true><<<dim3(1, gy), 256>>>(nullptr, W2, N, 256, 64);
    alpha_kernel<1><<<warpBlocks, 256>>>(a2s, a2d, N);
    agg_kernel<2, 1, false><<<warpBlocks, 256>>>(b2, N);

    // ---- mean over nodes + linear head ----
    zero_sum_kernel<<<1, 64>>>();
    colsum_kernel<<<NB, 64>>>(N);
    head_kernel<<<1, 64>>>(hw, hb, out, N);
}

// round 15
// speedup vs baseline: 1.6091x; 1.1764x over previous
#include <cuda_runtime.h>
#include <cuda_bf16.h>
#include <cstdint>

// ---------------- problem constants ----------------
#define NN     50000
#define IN_C   128
#define HID    64
#define HEADS  4
#define OUT_C  64
#define EMAX   800000
#define ETOT   (EMAX + NN)     // with self loops

// ---------------- scratch (device globals; no allocation allowed) ----------
__device__ float g_h [ (size_t)NN * (HEADS*HID) ]; // GEMM output / features h
__device__ float g_x [ (size_t)NN * (HEADS*HID) ]; // layer output / next GEMM input
__device__ float g_as[ NN * HEADS ];
__device__ float g_ad[ NN * HEADS ];
__device__ int   g_off[ NN + 1 ];
__device__ int   g_cnt[ NN ];
__device__ int   g_cur[ NN ];
__device__ int   g_srt[ ETOT ];
__device__ float g_sum[ HID ];
__device__ int   g_is64;          // edge_index dtype flag (auto-detected)
__device__ int   g_bsum[ 256 ];   // scan: per-block sums
__device__ int   g_bpre[ 256 ];   // scan: per-block exclusive prefixes

// ---------------- edge_index dtype detection ----------------
__global__ void detect_kernel(const int* __restrict__ ei32) {
    if (threadIdx.x == 0 && blockIdx.x == 0) {
        int odd_or = 0;
#pragma unroll
        for (int i = 0; i < 64; i++) odd_or |= ei32[2 * i + 1];
        g_is64 = (odd_or == 0) ? 1 : 0;
    }
}

__device__ __forceinline__ int edge_src(const int* ei32, int E, int i) {
    return g_is64 ? ei32[2 * i] : ei32[i];
}
__device__ __forceinline__ int edge_dst(const int* ei32, int E, int i) {
    return g_is64 ? ei32[2 * (E + i)] : ei32[E + i];
}

// ---------------- CSR build ----------------
__global__ void init_cnt_kernel(int n) {
    int i = blockIdx.x * blockDim.x + threadIdx.x;
    if (i < n) g_cnt[i] = 1;   // self loop
}

__global__ void hist_kernel(const int* __restrict__ ei, int E) {
    int i = blockIdx.x * blockDim.x + threadIdx.x;
    if (i < E) atomicAdd(&g_cnt[edge_dst(ei, E, i)], 1);
}

// --- 3-phase parallel scan over g_cnt -> g_off / g_cur ---
__global__ void scan1_kernel(int n) {        // per-block sums
    __shared__ int sh[256];
    int t = threadIdx.x;
    int i = blockIdx.x * 256 + t;
    sh[t] = (i < n) ? g_cnt[i] : 0;
    __syncthreads();
#pragma unroll
    for (int d = 128; d; d >>= 1) {
        if (t < d) sh[t] += sh[t + d];
        __syncthreads();
    }
    if (t == 0) g_bsum[blockIdx.x] = sh[0];
}

__global__ void scan2_kernel(int nb, int n) { // scan the (<=256) block sums
    __shared__ int sh[256];
    int t = threadIdx.x;
    int v = (t < nb) ? g_bsum[t] : 0;
    sh[t] = v;
    __syncthreads();
#pragma unroll
    for (int d = 1; d < 256; d <<= 1) {
        int u = (t >= d) ? sh[t - d] : 0;
        __syncthreads();
        sh[t] += u;
        __syncthreads();
    }
    g_bpre[t] = sh[t] - v;                    // exclusive
    if (t == 255) g_off[n] = sh[255];
}

__global__ void scan3_kernel(int n) {         // per-block rescan + base
    __shared__ int sh[256];
    int t = threadIdx.x;
    int i = blockIdx.x * 256 + t;
    int c = (i < n) ? g_cnt[i] : 0;
    sh[t] = c;
    __syncthreads();
#pragma unroll
    for (int d = 1; d < 256; d <<= 1) {
        int u = (t >= d) ? sh[t - d] : 0;
        __syncthreads();
        sh[t] += u;
        __syncthreads();
    }
    if (i < n) {
        int ex = sh[t] - c + g_bpre[blockIdx.x];
        g_off[i] = ex;
        g_cur[i] = ex;
    }
}

__global__ void scatter_kernel(const int* __restrict__ ei, int E, int n) {
    int i = blockIdx.x * blockDim.x + threadIdx.x;
    int total = E + n;
    if (i >= total) return;
    int s, d;
    if (i < E) { s = edge_src(ei, E, i); d = edge_dst(ei, E, i); }
    else       { s = d = i - E; }
    int pos = atomicAdd(&g_cur[d], 1);
    g_srt[pos] = s;
}

// ---------------- bf16 split helpers ----------------
// pack (f0,f1) -> hi = {bf16(f1) : bf16(f0)}, lo = {bf16(r1) : bf16(r0)}
// (cvt.rn.bf16x2.f32 d, a, b puts a in the UPPER half, b in the LOWER half)
__device__ __forceinline__ void pack_bf16_pair(float f0, float f1,
                                               unsigned& hi, unsigned& lo) {
    unsigned h;
    asm("cvt.rn.bf16x2.f32 %0, %1, %2;" : "=r"(h) : "f"(f1), "f"(f0));
    float h0 = __uint_as_float(h << 16);
    float h1 = __uint_as_float(h & 0xFFFF0000u);
    hi = h;
    asm("cvt.rn.bf16x2.f32 %0, %1, %2;" : "=r"(lo) : "f"(f1 - h1), "f"(f0 - h0));
}

__device__ __forceinline__ void mma_bf16(float* d, const unsigned* a, const unsigned* b) {
    asm volatile(
        "mma.sync.aligned.m16n8k16.row.col.f32.bf16.bf16.f32 "
        "{%0,%1,%2,%3}, {%4,%5,%6,%7}, {%8,%9}, {%0,%1,%2,%3};\n"
        : "+f"(d[0]), "+f"(d[1]), "+f"(d[2]), "+f"(d[3])
        : "r"(a[0]), "r"(a[1]), "r"(a[2]), "r"(a[3]), "r"(b[0]), "r"(b[1]));
}

// ---------------- GEMM (3-term split-bf16 mma.m16n8k16) --------------------
// g_h[N,M] = A[N,K] @ B[K,M].  BM=128 BN=64 BK=32, 8 warps, warp tile 32x32.
// Operands packed to bf16 hi/lo pairs along K at smem-fill time.
// D += Ah*Bh + Al*Bh + Ah*Bl  (per-product err ~2^-17).
#define PKS 20   // padded u32 stride (conflict-free: 20*gq+tg distinct mod 32)
template<bool FROM_GLOBAL>
__global__ __launch_bounds__(256) void mma_gemm_kernel(
    const float* __restrict__ Ain, const float* __restrict__ B,
    int Nrows, int K, int M)
{
    const float* A = FROM_GLOBAL ? g_x : Ain;
    float* C = g_h;
    __shared__ unsigned Ah[128][PKS], Al[128][PKS];  // [row][k-pair]
    __shared__ unsigned Bh[64][PKS],  Bl[64][PKS];   // [col][k-pair]

    int tid  = threadIdx.x;
    int lane = tid & 31;
    int wid  = tid >> 5;
    int row0 = blockIdx.y * 128;
    int col0 = blockIdx.x * 64;
    int wm = (wid >> 1) * 32;     // warp row offset in block tile
    int wn = (wid & 1) * 32;      // warp col offset
    int gq = lane >> 2;           // group id (0..7)
    int tg = lane & 3;            // thread-in-group (0..3)

    float acc[2][4][4];
#pragma unroll
    for (int mf = 0; mf < 2; mf++)
#pragma unroll
        for (int nf = 0; nf < 4; nf++)
#pragma unroll
            for (int e = 0; e < 4; e++) acc[mf][nf][e] = 0.f;

    for (int k0 = 0; k0 < K; k0 += 32) {
        // ---- A tile 128x32: 1024 float4 / 4 per thread; pack along K ----
#pragma unroll
        for (int i = 0; i < 4; i++) {
            int idx = tid + i * 256;
            int r   = idx >> 3;
            int c4  = idx & 7;          // float4 index within the 32-k row
            int grow = row0 + r;
            float4 v = make_float4(0.f, 0.f, 0.f, 0.f);
            if (grow < Nrows)
                v = *reinterpret_cast<const float4*>(A + (size_t)grow * K + k0 + c4 * 4);
            unsigned h0, l0, h1, l1;
            pack_bf16_pair(v.x, v.y, h0, l0);
            pack_bf16_pair(v.z, v.w, h1, l1);
            Ah[r][c4 * 2]     = h0;  Al[r][c4 * 2]     = l0;
            Ah[r][c4 * 2 + 1] = h1;  Al[r][c4 * 2 + 1] = l1;
        }
        // ---- B tile 32x64: thread (kp, c4) loads rows 2kp,2kp+1 ----
        {
            int kp = tid >> 4;          // k-pair 0..15
            int c4 = tid & 15;          // 4-col group 0..15
            const float* bp = B + (size_t)(k0 + 2 * kp) * M + col0 + c4 * 4;
            float4 v0 = *reinterpret_cast<const float4*>(bp);
            float4 v1 = *reinterpret_cast<const float4*>(bp + M);
            const float* p0 = &v0.x;
            const float* p1 = &v1.x;
#pragma unroll
            for (int j = 0; j < 4; j++) {
                unsigned h, l;
                pack_bf16_pair(p0[j], p1[j], h, l);   // lower = k even
                Bh[c4 * 4 + j][kp] = h;
                Bl[c4 * 4 + j][kp] = l;
            }
        }
        __syncthreads();

#pragma unroll
        for (int ks = 0; ks < 2; ks++) {     // two k16 steps per BK=32
            int kb = ks * 8;
            unsigned ah[2][4], al[2][4];
#pragma unroll
            for (int mf = 0; mf < 2; mf++) {
                int r = wm + mf * 16 + gq;
                ah[mf][0] = Ah[r][kb + tg];       al[mf][0] = Al[r][kb + tg];
                ah[mf][1] = Ah[r + 8][kb + tg];   al[mf][1] = Al[r + 8][kb + tg];
                ah[mf][2] = Ah[r][kb + tg + 4];   al[mf][2] = Al[r][kb + tg + 4];
                ah[mf][3] = Ah[r + 8][kb + tg + 4]; al[mf][3] = Al[r + 8][kb + tg + 4];
            }
            unsigned bh[4][2], bl[4][2];
#pragma unroll
            for (int nf = 0; nf < 4; nf++) {
                int nn = wn + nf * 8 + gq;
                bh[nf][0] = Bh[nn][kb + tg];      bl[nf][0] = Bl[nn][kb + tg];
                bh[nf][1] = Bh[nn][kb + tg + 4];  bl[nf][1] = Bl[nn][kb + tg + 4];
            }
#pragma unroll
            for (int mf = 0; mf < 2; mf++)
#pragma unroll
                for (int nf = 0; nf < 4; nf++) {
                    mma_bf16(acc[mf][nf], ah[mf], bh[nf]);
                    mma_bf16(acc[mf][nf], al[mf], bh[nf]);
                    mma_bf16(acc[mf][nf], ah[mf], bl[nf]);
                }
        }
        __syncthreads();
    }

    // ---- epilogue: c0:(gq,2tg) c1:(gq,2tg+1) c2:(gq+8,2tg) c3:(gq+8,2tg+1)
#pragma unroll
    for (int mf = 0; mf < 2; mf++) {
#pragma unroll
        for (int nf = 0; nf < 4; nf++) {
            int r = row0 + wm + mf * 16 + gq;
            int c = col0 + wn + nf * 8 + tg * 2;
            if (r < Nrows)
                *reinterpret_cast<float2*>(C + (size_t)r * M + c) =
                    make_float2(acc[mf][nf][0], acc[mf][nf][1]);
            if (r + 8 < Nrows)
                *reinterpret_cast<float2*>(C + (size_t)(r + 8) * M + c) =
                    make_float2(acc[mf][nf][2], acc[mf][nf][3]);
        }
    }
}

// ---------------- attention coefficients: alpha_s/alpha_d per node ----------
// reads g_h, writes g_as/g_ad
template<int H>
__global__ void alpha_kernel(const float* __restrict__ a_s,
                             const float* __restrict__ a_d, int n)
{
    int w = (blockIdx.x * blockDim.x + threadIdx.x) >> 5;
    int lane = threadIdx.x & 31;
    if (w >= n) return;
    constexpr int FPL = 2 * H;
    float ps[H], pd[H];
#pragma unroll
    for (int hh = 0; hh < H; hh++) { ps[hh] = 0.f; pd[hh] = 0.f; }
    const float* row = g_h + (size_t)w * (H * 64);
#pragma unroll
    for (int j = 0; j < FPL; j++) {
        float v = row[lane + 32 * j];
        int hh = j >> 1;
        int c  = lane + 32 * (j & 1);
        ps[hh] += v * a_s[hh * 64 + c];
        pd[hh] += v * a_d[hh * 64 + c];
    }
#pragma unroll
    for (int hh = 0; hh < H; hh++) {
        float s = ps[hh], d = pd[hh];
#pragma unroll
        for (int o = 16; o; o >>= 1) {
            s += __shfl_xor_sync(0xffffffffu, s, o);
            d += __shfl_xor_sync(0xffffffffu, d, o);
        }
        if (lane == 0) { g_as[w * H + hh] = s; g_ad[w * H + hh] = d; }
    }
}

// ---------------- fused edge softmax + aggregation (one warp per dst) -------
// reads g_h/g_as/g_ad/g_off/g_srt, writes g_x
template<int FPL, int H, bool RELU>
__global__ __launch_bounds__(256) void agg_kernel(
    const float* __restrict__ bias, int n)
{
    int w = (blockIdx.x * blockDim.x + threadIdx.x) >> 5;
    int lane = threadIdx.x & 31;
    if (w >= n) return;
    constexpr int FEAT = FPL * 32;

    float adv[H];
#pragma unroll
    for (int hh = 0; hh < H; hh++) adv[hh] = g_ad[w * H + hh];

    float m[H], den[H], acc[FPL];
#pragma unroll
    for (int hh = 0; hh < H; hh++) { m[hh] = -1e30f; den[hh] = 0.f; }
#pragma unroll
    for (int j = 0; j < FPL; j++) acc[j] = 0.f;

    int e1 = g_off[w + 1];
    for (int e = g_off[w]; e < e1; e++) {
        int s = g_srt[e];                       // same for all lanes -> broadcast
        const float* hr = g_h + (size_t)s * FEAT;
        float v[FPL];
#pragma unroll
        for (int j = 0; j < FPL; j++) v[j] = hr[lane + 32 * j];

        float asv[H];
        if constexpr (H == 4) {
            float4 t = *reinterpret_cast<const float4*>(g_as + (size_t)s * 4);
            asv[0] = t.x; asv[1] = t.y; asv[2] = t.z; asv[3] = t.w;
        } else {
            asv[0] = g_as[s];
        }
#pragma unroll
        for (int hh = 0; hh < H; hh++) {
            float eh = asv[hh] + adv[hh];
            eh = (eh > 0.f) ? eh : 0.2f * eh;     // leaky_relu(0.2)
            float wgt;
            if (eh > m[hh]) {
                float sc = __expf(m[hh] - eh);    // exp(-inf)=0 on first edge
                den[hh] = den[hh] * sc + 1.f;
                acc[2 * hh]     *= sc;
                acc[2 * hh + 1] *= sc;
                m[hh] = eh;
                wgt = 1.f;
            } else {
                wgt = __expf(eh - m[hh]);
                den[hh] += wgt;
            }
            acc[2 * hh]     += wgt * v[2 * hh];
            acc[2 * hh + 1] += wgt * v[2 * hh + 1];
        }
    }
#pragma unroll
    for (int j = 0; j < FPL; j++) {
        int col = lane + 32 * j;
        float o = acc[j] / den[j >> 1] + bias[col];
        if (RELU) o = fmaxf(o, 0.f);
        g_x[(size_t)w * FEAT + col] = o;
    }
}

// ---------------- mean over nodes + linear head ----------------
__global__ void zero_sum_kernel() {
    g_sum[threadIdx.x] = 0.f;
}

__global__ void colsum_kernel(int n) {
    int col = threadIdx.x;                 // 64 threads
    int r0 = blockIdx.x * 256;
    int r1 = r0 + 256; if (r1 > n) r1 = n;
    float s = 0.f;
    for (int r = r0; r < r1; r++) s += g_x[(size_t)r * 64 + col];
    atomicAdd(&g_sum[col], s);
}

__global__ void head_kernel(const float* __restrict__ hw,
                            const float* __restrict__ hb,
                            float* __restrict__ out, int n) {
    __shared__ float g[64];
    int t = threadIdx.x;
    g[t] = g_sum[t] / (float)n;
    __syncthreads();
    float o = hb[t];
#pragma unroll
    for (int c = 0; c < 64; c++) o += g[c] * hw[c * 64 + t];
    out[t] = o;
}

// ---------------- launch (kernel launches ONLY; graph-capturable) ----------
extern "C" void kernel_launch(void* const* d_in, const int* in_sizes, int n_in,
                              void* d_out, int out_size) {
    const float* x   = (const float*)d_in[0];
    const int*   ei  = (const int*)d_in[1];     // int32 OR int64 (auto-detected)
    const float* W0  = (const float*)d_in[2];
    const float* a0s = (const float*)d_in[3];
    const float* a0d = (const float*)d_in[4];
    const float* b0  = (const float*)d_in[5];
    const float* W1  = (const float*)d_in[6];
    const float* a1s = (const float*)d_in[7];
    const float* a1d = (const float*)d_in[8];
    const float* b1  = (const float*)d_in[9];
    const float* W2  = (const float*)d_in[10];
    const float* a2s = (const float*)d_in[11];
    const float* a2d = (const float*)d_in[12];
    const float* b2  = (const float*)d_in[13];
    const float* hw  = (const float*)d_in[14];
    const float* hb  = (const float*)d_in[15];
    float* out = (float*)d_out;

    const int N = in_sizes[0] / IN_C;
    const int E = in_sizes[1] / 2;   // element count is dtype-independent

    // ---- CSR by dst (recomputed each launch; deterministic work) ----
    const int NB = (N + 255) / 256;
    detect_kernel<<<1, 32>>>(ei);
    init_cnt_kernel<<<NB, 256>>>(N);
    hist_kernel<<<(E + 255) / 256, 256>>>(ei, E);
    scan1_kernel<<<NB, 256>>>(N);
    scan2_kernel<<<1, 256>>>(NB, N);
    scan3_kernel<<<NB, 256>>>(N);
    scatter_kernel<<<((E + N) + 255) / 256, 256>>>(ei, E, N);

    const int warpBlocks = (N * 32 + 255) / 256;
    const int gy = (N + 127) / 128;

    // ---- layer 0: 128 -> 4x64 ----
    mma_gemm_kernel<false><<<dim3(4, gy), 256>>>(x, W0, N, 128, 256);
    alpha_kernel<4><<<warpBlocks, 256>>>(a0s, a0d, N);
    agg_kernel<8, 4, true><<<warpBlocks, 256>>>(b0, N);

    // ---- layer 1: 256 -> 4x64 ----
    mma_gemm_kernel<true><<<dim3(4, gy), 256>>>(nullptr, W1, N, 256, 256);
    alpha_kernel<4><<<warpBlocks, 256>>>(a1s, a1d, N);
    agg_kernel<8, 4, true><<<warpBlocks, 256>>>(b1, N);

    // ---- layer 2: 256 -> 1x64 (no relu) ----
    mma_gemm_kernel<true><<<dim3(1, gy), 256>>>(nullptr, W2, N, 256, 64);
    alpha_kernel<1><<<warpBlocks, 256>>>(a2s, a2d, N);
    agg_kernel<2, 1, false><<<warpBlocks, 256>>>(b2, N);

    // ---- mean over nodes + linear head ----
    zero_sum_kernel<<<1, 64>>>();
    colsum_kernel<<<NB, 64>>>(N);
    head_kernel<<<1, 64>>>(hw, hb, out, N);
}